// round 13
// baseline (speedup 1.0000x reference)
#include <cuda_runtime.h>
#include <cuda_fp16.h>
#include <cstdint>
#include <cstddef>

#define DIN 128
#define NMAX 100000
#define EMAX 1600000
#define SCAN_B 1024

// ---------------- scratch (device globals; no allocation allowed) ----------
__device__ int    g_cnt [NMAX];
__device__ int    g_fill[NMAX];
__device__ int    g_rowptr[NMAX + 1];
__device__ int    g_bsums[128];
__device__ int2   g_cw[EMAX];                   // CSR packed (col, w-bits)
__device__ float  g_dinv[NMAX];
__device__ __half g_T16[(size_t)NMAX * 128];    // h @ W (fp16, gather payload)
__device__ float  g_H[(size_t)NMAX * 128];      // layer activation (fp32)
__device__ float  g_Z[(size_t)NMAX * 64];       // final embeddings (fp32)

// ---------------- small PTX helpers ----------------------------------------
__device__ __forceinline__ unsigned long long ffma2(unsigned long long a,
                                                    unsigned long long b,
                                                    unsigned long long c) {
    unsigned long long d;
    asm("fma.rn.f32x2 %0, %1, %2, %3;" : "=l"(d) : "l"(a), "l"(b), "l"(c));
    return d;
}
__device__ __forceinline__ float2 unpack2(unsigned long long v) {
    float2 f;
    asm("mov.b64 {%0,%1}, %2;" : "=f"(f.x), "=f"(f.y) : "l"(v));
    return f;
}
__device__ __forceinline__ unsigned long long dup2(float w) {
    unsigned long long d;
    asm("mov.b64 %0, {%1,%1};" : "=l"(d) : "f"(w));
    return d;
}

// ---------------- CSR build --------------------------------------------------
__global__ void k_zero(int* cnt, int* fill, int n) {
    int i = blockIdx.x * blockDim.x + threadIdx.x;
    if (i < n) { cnt[i] = 0; fill[i] = 0; }
}

__global__ void k_count(const int* __restrict__ dst, int* cnt, int E) {
    int i = blockIdx.x * blockDim.x + threadIdx.x;
    if (i < E) atomicAdd(&cnt[dst[i]], 1);
}

__global__ void k_dinv(const int* __restrict__ cnt, float* __restrict__ dinv, int n) {
    int i = blockIdx.x * blockDim.x + threadIdx.x;
    if (i < n) dinv[i] = rsqrtf((float)(cnt[i] + 1));
}

__global__ void k_scan1(const int* __restrict__ cnt, int* __restrict__ rowptr,
                        int* __restrict__ bsums, int n) {
    __shared__ int sh[SCAN_B];
    int t = threadIdx.x;
    int i = blockIdx.x * SCAN_B + t;
    int v = (i < n) ? cnt[i] : 0;
    sh[t] = v;
    __syncthreads();
    for (int o = 1; o < SCAN_B; o <<= 1) {
        int x = (t >= o) ? sh[t - o] : 0;
        __syncthreads();
        sh[t] += x;
        __syncthreads();
    }
    if (i < n) rowptr[i] = sh[t] - v;
    if (t == SCAN_B - 1) bsums[blockIdx.x] = sh[t];
}

__global__ void k_scan2(int* bsums, int nb, int* rowptr, int n) {
    int off = 0;
    for (int b = 0; b < nb; b++) { int s = bsums[b]; bsums[b] = off; off += s; }
    rowptr[n] = off;
}

__global__ void k_scan3(int* __restrict__ rowptr, const int* __restrict__ bsums, int n) {
    int i = blockIdx.x * blockDim.x + threadIdx.x;
    if (i < n) rowptr[i] += bsums[i >> 10];
}

__global__ void k_fill(const int* __restrict__ src, const int* __restrict__ dst,
                       const int* __restrict__ rowptr, int* __restrict__ fill,
                       const float* __restrict__ dinv,
                       int2* __restrict__ cw, int E) {
    int e = blockIdx.x * blockDim.x + threadIdx.x;
    if (e >= E) return;
    int s = src[e], d = dst[e];
    int pos = rowptr[d] + atomicAdd(&fill[d], 1);
    cw[pos] = make_int2(s, __float_as_int(dinv[s] * dinv[d]));
}

// ---------------- GEMM: fp32 in, fp16 out; register prefetch ---------------
template <int NC>
__global__ void __launch_bounds__(128, 2)
k_gemm3(const float* __restrict__ X, const float* __restrict__ W,
        __half* __restrict__ T, int nrows) {
    constexpr int BM = 128, KC = 16, XROW = BM + 4;
    constexpr int TNT = NC / 32;          // 4 (NC=128) / 2 (NC=64)
    constexpr int WS  = KC * NC / 512;    // 4 / 2
    constexpr int NCHUNK = DIN / KC;      // 8

    __shared__ float Xs[KC][XROW];
    __shared__ float Ws[KC][NC];

    const int tid  = threadIdx.x;
    const int warp = tid >> 5;
    const int lane = tid & 31;
    const int warpM = warp & 1, warpN = warp >> 1;
    const int lr = lane & 3,   lc = lane >> 2;
    const int row0 = blockIdx.x * BM;
    const int rb = warpM * 64 + lr * 4;
    const int cb = warpN * (NC / 2) + lc * 2;

    const int wk = (tid * 4) / NC;
    const int wc4 = tid % (NC / 4);
    const int xr = tid >> 2, xkq = tid & 3;
    const float* Wp = W + (size_t)wk * NC + wc4 * 4;

    float4 wreg[WS], xreg[4];
    #pragma unroll
    for (int s = 0; s < WS; s++)
        wreg[s] = *(const float4*)(Wp + (size_t)(s * (512 / NC)) * NC);
    #pragma unroll
    for (int t = 0; t < 4; t++) {
        int rr2 = row0 + xr + t * 32; if (rr2 >= nrows) rr2 = nrows - 1;
        xreg[t] = *(const float4*)(X + (size_t)rr2 * DIN + xkq * 4);
    }

    unsigned long long acc2[8][2 * TNT];
    #pragma unroll
    for (int i = 0; i < 8; i++)
        #pragma unroll
        for (int j = 0; j < 2 * TNT; j++) acc2[i][j] = 0ull;

    for (int chunk = 0; chunk < NCHUNK; chunk++) {
        #pragma unroll
        for (int s = 0; s < WS; s++)
            *(float4*)&Ws[wk + s * (512 / NC)][wc4 * 4] = wreg[s];
        #pragma unroll
        for (int t = 0; t < 4; t++) {
            int r = xr + t * 32;
            Xs[xkq * 4 + 0][r] = xreg[t].x;
            Xs[xkq * 4 + 1][r] = xreg[t].y;
            Xs[xkq * 4 + 2][r] = xreg[t].z;
            Xs[xkq * 4 + 3][r] = xreg[t].w;
        }
        __syncthreads();

        if (chunk + 1 < NCHUNK) {
            int kc = (chunk + 1) * KC;
            #pragma unroll
            for (int s = 0; s < WS; s++)
                wreg[s] = *(const float4*)(Wp + (size_t)(kc + s * (512 / NC)) * NC);
            #pragma unroll
            for (int t = 0; t < 4; t++) {
                int rr2 = row0 + xr + t * 32; if (rr2 >= nrows) rr2 = nrows - 1;
                xreg[t] = *(const float4*)(X + (size_t)rr2 * DIN + kc + xkq * 4);
            }
        }

        #pragma unroll
        for (int k = 0; k < KC; k++) {
            unsigned long long a2[8], b2[2 * TNT];
            #pragma unroll
            for (int s = 0; s < 4; s++) {
                ulonglong2 A = *(const ulonglong2*)&Xs[k][rb + 16 * s];
                a2[2 * s] = A.x; a2[2 * s + 1] = A.y;
            }
            #pragma unroll
            for (int t = 0; t < TNT; t++) {
                float2 bv = *(const float2*)&Ws[k][cb + 16 * t];
                b2[2 * t]     = dup2(bv.x);
                b2[2 * t + 1] = dup2(bv.y);
            }
            #pragma unroll
            for (int i = 0; i < 8; i++)
                #pragma unroll
                for (int j = 0; j < 2 * TNT; j++)
                    acc2[i][j] = ffma2(a2[i], b2[j], acc2[i][j]);
        }
        __syncthreads();
    }

    // epilogue: convert fp32 -> half2 pairs
    #pragma unroll
    for (int i = 0; i < 8; i++) {
        int s = i >> 1, p = i & 1;
        int re = row0 + rb + 16 * s + 2 * p;
        #pragma unroll
        for (int t = 0; t < TNT; t++) {
            float2 e0 = unpack2(acc2[i][2 * t]);
            float2 e1 = unpack2(acc2[i][2 * t + 1]);
            int c = cb + 16 * t;
            if (re < nrows)
                *(__half2*)(T + (size_t)re * NC + c) = __floats2half2_rn(e0.x, e1.x);
            if (re + 1 < nrows)
                *(__half2*)(T + (size_t)(re + 1) * NC + c) = __floats2half2_rn(e0.y, e1.y);
        }
    }
}

// ---------------- aggregate (fp16 gather, fp32 accumulate) ------------------
#define NPB 32

template <bool RELU>
__global__ void k_aggregate128(const __half* __restrict__ T,
                               const int* __restrict__ rowptr,
                               const int2* __restrict__ cw,
                               const float* __restrict__ dinv,
                               const float* __restrict__ bias,
                               float* __restrict__ H, int n) {
    __shared__ int ctr;
    if (threadIdx.x == 0) ctr = 0;
    __syncthreads();
    const int base = blockIdx.x * NPB;
    const int lane = threadIdx.x & 31;

    for (;;) {
        int k;
        if (lane == 0) k = atomicAdd(&ctr, 1);
        k = __shfl_sync(0xFFFFFFFFu, k, 0);
        if (k >= NPB) break;
        int i = base + k;
        if (i >= n) break;

        float dn = dinv[i]; dn *= dn;
        // self-loop: 4 halves per lane (8B)
        uint2 tv = __ldg((const uint2*)(T + (size_t)i * 128) + lane);
        float2 t0 = __half22float2(*(__half2*)&tv.x);
        float2 t1 = __half22float2(*(__half2*)&tv.y);
        float4 acc = make_float4(t0.x * dn, t0.y * dn, t1.x * dn, t1.y * dn);
        float4 acc1 = make_float4(0.f, 0.f, 0.f, 0.f);

        int j = rowptr[i], end = rowptr[i + 1];
        for (; j + 2 <= end; j += 2) {
            int2 e0 = __ldg(cw + j);
            int2 e1 = __ldg(cw + j + 1);
            float w0 = __int_as_float(e0.y), w1 = __int_as_float(e1.y);
            uint2 r0 = __ldg((const uint2*)(T + (size_t)e0.x * 128) + lane);
            uint2 r1 = __ldg((const uint2*)(T + (size_t)e1.x * 128) + lane);
            float2 a0 = __half22float2(*(__half2*)&r0.x);
            float2 a1 = __half22float2(*(__half2*)&r0.y);
            float2 b0 = __half22float2(*(__half2*)&r1.x);
            float2 b1 = __half22float2(*(__half2*)&r1.y);
            acc.x  = fmaf(w0, a0.x, acc.x);  acc.y  = fmaf(w0, a0.y, acc.y);
            acc.z  = fmaf(w0, a1.x, acc.z);  acc.w  = fmaf(w0, a1.y, acc.w);
            acc1.x = fmaf(w1, b0.x, acc1.x); acc1.y = fmaf(w1, b0.y, acc1.y);
            acc1.z = fmaf(w1, b1.x, acc1.z); acc1.w = fmaf(w1, b1.y, acc1.w);
        }
        if (j < end) {
            int2 e0 = __ldg(cw + j);
            float w0 = __int_as_float(e0.y);
            uint2 r0 = __ldg((const uint2*)(T + (size_t)e0.x * 128) + lane);
            float2 a0 = __half22float2(*(__half2*)&r0.x);
            float2 a1 = __half22float2(*(__half2*)&r0.y);
            acc.x = fmaf(w0, a0.x, acc.x); acc.y = fmaf(w0, a0.y, acc.y);
            acc.z = fmaf(w0, a1.x, acc.z); acc.w = fmaf(w0, a1.y, acc.w);
        }
        acc.x += acc1.x; acc.y += acc1.y; acc.z += acc1.z; acc.w += acc1.w;

        float4 b = __ldg((const float4*)bias + lane);
        acc.x += b.x; acc.y += b.y; acc.z += b.z; acc.w += b.w;
        if (RELU) {
            acc.x = fmaxf(acc.x, 0.f); acc.y = fmaxf(acc.y, 0.f);
            acc.z = fmaxf(acc.z, 0.f); acc.w = fmaxf(acc.w, 0.f);
        }
        ((float4*)(H + (size_t)i * 128))[lane] = acc;
    }
}

__global__ void k_aggregate64(const __half* __restrict__ T,
                              const int* __restrict__ rowptr,
                              const int2* __restrict__ cw,
                              const float* __restrict__ dinv,
                              const float* __restrict__ bias,
                              float* __restrict__ Z, int n) {
    __shared__ int ctr;
    if (threadIdx.x == 0) ctr = 0;
    __syncthreads();
    const int base = blockIdx.x * NPB;
    const int lane = threadIdx.x & 31;

    for (;;) {
        int k;
        if (lane == 0) k = atomicAdd(&ctr, 1);
        k = __shfl_sync(0xFFFFFFFFu, k, 0);
        if (k >= NPB) break;
        int i = base + k;
        if (i >= n) break;

        float dn = dinv[i]; dn *= dn;
        unsigned tv = __ldg((const unsigned*)(T + (size_t)i * 64) + lane);
        float2 t0 = __half22float2(*(__half2*)&tv);
        float2 acc = make_float2(t0.x * dn, t0.y * dn);
        float2 acc1 = make_float2(0.f, 0.f);

        int j = rowptr[i], end = rowptr[i + 1];
        for (; j + 2 <= end; j += 2) {
            int2 e0 = __ldg(cw + j);
            int2 e1 = __ldg(cw + j + 1);
            float w0 = __int_as_float(e0.y), w1 = __int_as_float(e1.y);
            unsigned r0 = __ldg((const unsigned*)(T + (size_t)e0.x * 64) + lane);
            unsigned r1 = __ldg((const unsigned*)(T + (size_t)e1.x * 64) + lane);
            float2 a0 = __half22float2(*(__half2*)&r0);
            float2 b0 = __half22float2(*(__half2*)&r1);
            acc.x  = fmaf(w0, a0.x, acc.x);  acc.y  = fmaf(w0, a0.y, acc.y);
            acc1.x = fmaf(w1, b0.x, acc1.x); acc1.y = fmaf(w1, b0.y, acc1.y);
        }
        if (j < end) {
            int2 e0 = __ldg(cw + j);
            float w0 = __int_as_float(e0.y);
            unsigned r0 = __ldg((const unsigned*)(T + (size_t)e0.x * 64) + lane);
            float2 a0 = __half22float2(*(__half2*)&r0);
            acc.x = fmaf(w0, a0.x, acc.x); acc.y = fmaf(w0, a0.y, acc.y);
        }
        acc.x += acc1.x; acc.y += acc1.y;

        float2 b = __ldg((const float2*)bias + lane);
        acc.x += b.x; acc.y += b.y;
        ((float2*)(Z + (size_t)i * 64))[lane] = acc;
    }
}

// ---------------- decode -----------------------------------------------------
__global__ void k_decode(const float* __restrict__ Z, const int* __restrict__ eli,
                         float* __restrict__ out, int EL) {
    int gt = blockIdx.x * blockDim.x + threadIdx.x;
    int p = gt >> 5;
    int lane = gt & 31;
    if (p >= EL) return;
    int a = eli[p];
    int b = eli[EL + p];
    float2 za = __ldg((const float2*)(Z + (size_t)a * 64) + lane);
    float2 zb = __ldg((const float2*)(Z + (size_t)b * 64) + lane);
    float s = za.x * zb.x + za.y * zb.y;
    #pragma unroll
    for (int o = 16; o; o >>= 1) s += __shfl_xor_sync(0xFFFFFFFFu, s, o);
    if (lane == 0) out[p] = s;
}

// ---------------- launch ----------------------------------------------------
extern "C" void kernel_launch(void* const* d_in, const int* in_sizes, int n_in,
                              void* d_out, int out_size) {
    const float* x   = (const float*)d_in[0];
    const int*   ei  = (const int*)d_in[1];
    const int*   eli = (const int*)d_in[2];
    const float* W1 = (const float*)d_in[3];
    const float* b1 = (const float*)d_in[4];
    const float* W2 = (const float*)d_in[5];
    const float* b2 = (const float*)d_in[6];
    const float* W3 = (const float*)d_in[7];
    const float* b3 = (const float*)d_in[8];
    float* out = (float*)d_out;

    const int N  = in_sizes[0] / DIN;
    const int E  = in_sizes[1] / 2;
    const int EL = in_sizes[2] / 2;
    const int* src = ei;
    const int* dst = ei + E;

    int *cnt, *fill, *rowptr, *bsums;
    int2* cw;
    float *dinv, *H, *Z;
    __half* T;
    cudaGetSymbolAddress((void**)&cnt,    g_cnt);
    cudaGetSymbolAddress((void**)&fill,   g_fill);
    cudaGetSymbolAddress((void**)&rowptr, g_rowptr);
    cudaGetSymbolAddress((void**)&bsums,  g_bsums);
    cudaGetSymbolAddress((void**)&cw,     g_cw);
    cudaGetSymbolAddress((void**)&dinv,   g_dinv);
    cudaGetSymbolAddress((void**)&T,      g_T16);
    cudaGetSymbolAddress((void**)&H,      g_H);
    cudaGetSymbolAddress((void**)&Z,      g_Z);

    const int TB = 256;
    const int nblk = (N + SCAN_B - 1) / SCAN_B;
    const int gblocks = (N + 127) / 128;
    const int ablocks = (N + NPB - 1) / NPB;

    k_zero <<<(N + TB - 1) / TB, TB>>>(cnt, fill, N);
    k_count<<<(E + TB - 1) / TB, TB>>>(dst, cnt, E);
    k_dinv <<<(N + TB - 1) / TB, TB>>>(cnt, dinv, N);
    k_gemm3<128><<<gblocks, 128>>>(x, W1, T, N);          // layer-1 GEMM
    k_scan1<<<nblk, SCAN_B>>>(cnt, rowptr, bsums, N);
    k_scan2<<<1, 1>>>(bsums, nblk, rowptr, N);
    k_scan3<<<(N + TB - 1) / TB, TB>>>(rowptr, bsums, N);
    k_fill <<<(E + TB - 1) / TB, TB>>>(src, dst, rowptr, fill, dinv, cw, E);

    // layer 1 aggregate
    k_aggregate128<true><<<ablocks, TB>>>(T, rowptr, cw, dinv, b1, H, N);
    // layer 2
    k_gemm3<128><<<gblocks, 128>>>(H, W2, T, N);
    k_aggregate128<true><<<ablocks, TB>>>(T, rowptr, cw, dinv, b2, H, N);
    // layer 3
    k_gemm3<64><<<gblocks, 128>>>(H, W3, T, N);
    k_aggregate64<<<ablocks, TB>>>(T, rowptr, cw, dinv, b3, Z, N);

    // decode
    k_decode<<<(int)(((size_t)EL * 32 + TB - 1) / TB), TB>>>(Z, eli, out, EL);
}

// round 14
// speedup vs baseline: 1.5162x; 1.5162x over previous
#include <cuda_runtime.h>
#include <cuda_fp16.h>
#include <cstdint>
#include <cstddef>

#define DIN 128
#define NMAX 100000
#define EMAX 1600000
#define SCAN_B 1024

// ---------------- scratch (device globals; no allocation allowed) ----------
__device__ int    g_cnt [NMAX];
__device__ int    g_fill[NMAX];
__device__ int    g_rowptr[NMAX + 1];
__device__ int    g_bsums[128];
__device__ int2   g_cw[EMAX];                   // CSR packed (col, w-bits)
__device__ float  g_dinv[NMAX];
__device__ __half g_T16[(size_t)NMAX * 128];    // h @ W (fp16, gather payload)
__device__ float  g_H[(size_t)NMAX * 128];      // layer activation (fp32)
__device__ float  g_Z[(size_t)NMAX * 64];       // final embeddings (fp32)

// ---------------- small PTX helpers ----------------------------------------
__device__ __forceinline__ unsigned long long ffma2(unsigned long long a,
                                                    unsigned long long b,
                                                    unsigned long long c) {
    unsigned long long d;
    asm("fma.rn.f32x2 %0, %1, %2, %3;" : "=l"(d) : "l"(a), "l"(b), "l"(c));
    return d;
}
__device__ __forceinline__ float2 unpack2(unsigned long long v) {
    float2 f;
    asm("mov.b64 {%0,%1}, %2;" : "=f"(f.x), "=f"(f.y) : "l"(v));
    return f;
}
__device__ __forceinline__ unsigned long long dup2(float w) {
    unsigned long long d;
    asm("mov.b64 %0, {%1,%1};" : "=l"(d) : "f"(w));
    return d;
}

// ---------------- CSR build --------------------------------------------------
__global__ void k_zero_count(const int* __restrict__ dst, int* cnt, int* fill,
                             int n, int E) {
    int i = blockIdx.x * blockDim.x + threadIdx.x;
    if (i < n) { cnt[i] = 0; fill[i] = 0; }
    // grid-stride second phase happens in k_count (separate launch keeps order)
}

__global__ void k_count(const int* __restrict__ dst, int* cnt, int E) {
    int i = blockIdx.x * blockDim.x + threadIdx.x;
    if (i < E) atomicAdd(&cnt[dst[i]], 1);
}

__global__ void k_dinv(const int* __restrict__ cnt, float* __restrict__ dinv, int n) {
    int i = blockIdx.x * blockDim.x + threadIdx.x;
    if (i < n) dinv[i] = rsqrtf((float)(cnt[i] + 1));
}

__global__ void k_scan1(const int* __restrict__ cnt, int* __restrict__ rowptr,
                        int* __restrict__ bsums, int n) {
    __shared__ int sh[SCAN_B];
    int t = threadIdx.x;
    int i = blockIdx.x * SCAN_B + t;
    int v = (i < n) ? cnt[i] : 0;
    sh[t] = v;
    __syncthreads();
    for (int o = 1; o < SCAN_B; o <<= 1) {
        int x = (t >= o) ? sh[t - o] : 0;
        __syncthreads();
        sh[t] += x;
        __syncthreads();
    }
    if (i < n) rowptr[i] = sh[t] - v;
    if (t == SCAN_B - 1) bsums[blockIdx.x] = sh[t];
}

__global__ void k_scan2(int* bsums, int nb, int* rowptr, int n) {
    int off = 0;
    for (int b = 0; b < nb; b++) { int s = bsums[b]; bsums[b] = off; off += s; }
    rowptr[n] = off;
}

__global__ void k_scan3(int* __restrict__ rowptr, const int* __restrict__ bsums, int n) {
    int i = blockIdx.x * blockDim.x + threadIdx.x;
    if (i < n) rowptr[i] += bsums[i >> 10];
}

__global__ void k_fill(const int* __restrict__ src, const int* __restrict__ dst,
                       const int* __restrict__ rowptr, int* __restrict__ fill,
                       const float* __restrict__ dinv,
                       int2* __restrict__ cw, int E) {
    int e = blockIdx.x * blockDim.x + threadIdx.x;
    if (e >= E) return;
    int s = src[e], d = dst[e];
    int pos = rowptr[d] + atomicAdd(&fill[d], 1);
    cw[pos] = make_int2(s, __float_as_int(dinv[s] * dinv[d]));
}

// ---------------- GEMM: fp32 in, fp16 out; register prefetch ---------------
template <int NC>
__global__ void __launch_bounds__(128, 2)
k_gemm3(const float* __restrict__ X, const float* __restrict__ W,
        __half* __restrict__ T, int nrows) {
    constexpr int BM = 128, KC = 16, XROW = BM + 4;
    constexpr int TNT = NC / 32;          // 4 (NC=128) / 2 (NC=64)
    constexpr int WS  = KC * NC / 512;    // 4 / 2
    constexpr int NCHUNK = DIN / KC;      // 8

    __shared__ float Xs[KC][XROW];
    __shared__ float Ws[KC][NC];

    const int tid  = threadIdx.x;
    const int warp = tid >> 5;
    const int lane = tid & 31;
    const int warpM = warp & 1, warpN = warp >> 1;
    const int lr = lane & 3,   lc = lane >> 2;
    const int row0 = blockIdx.x * BM;
    const int rb = warpM * 64 + lr * 4;
    const int cb = warpN * (NC / 2) + lc * 2;

    const int wk = (tid * 4) / NC;
    const int wc4 = tid % (NC / 4);
    const int xr = tid >> 2, xkq = tid & 3;
    const float* Wp = W + (size_t)wk * NC + wc4 * 4;

    float4 wreg[WS], xreg[4];
    #pragma unroll
    for (int s = 0; s < WS; s++)
        wreg[s] = *(const float4*)(Wp + (size_t)(s * (512 / NC)) * NC);
    #pragma unroll
    for (int t = 0; t < 4; t++) {
        int rr2 = row0 + xr + t * 32; if (rr2 >= nrows) rr2 = nrows - 1;
        xreg[t] = *(const float4*)(X + (size_t)rr2 * DIN + xkq * 4);
    }

    unsigned long long acc2[8][2 * TNT];
    #pragma unroll
    for (int i = 0; i < 8; i++)
        #pragma unroll
        for (int j = 0; j < 2 * TNT; j++) acc2[i][j] = 0ull;

    for (int chunk = 0; chunk < NCHUNK; chunk++) {
        #pragma unroll
        for (int s = 0; s < WS; s++)
            *(float4*)&Ws[wk + s * (512 / NC)][wc4 * 4] = wreg[s];
        #pragma unroll
        for (int t = 0; t < 4; t++) {
            int r = xr + t * 32;
            Xs[xkq * 4 + 0][r] = xreg[t].x;
            Xs[xkq * 4 + 1][r] = xreg[t].y;
            Xs[xkq * 4 + 2][r] = xreg[t].z;
            Xs[xkq * 4 + 3][r] = xreg[t].w;
        }
        __syncthreads();

        if (chunk + 1 < NCHUNK) {
            int kc = (chunk + 1) * KC;
            #pragma unroll
            for (int s = 0; s < WS; s++)
                wreg[s] = *(const float4*)(Wp + (size_t)(kc + s * (512 / NC)) * NC);
            #pragma unroll
            for (int t = 0; t < 4; t++) {
                int rr2 = row0 + xr + t * 32; if (rr2 >= nrows) rr2 = nrows - 1;
                xreg[t] = *(const float4*)(X + (size_t)rr2 * DIN + kc + xkq * 4);
            }
        }

        #pragma unroll
        for (int k = 0; k < KC; k++) {
            unsigned long long a2[8], b2[2 * TNT];
            #pragma unroll
            for (int s = 0; s < 4; s++) {
                ulonglong2 A = *(const ulonglong2*)&Xs[k][rb + 16 * s];
                a2[2 * s] = A.x; a2[2 * s + 1] = A.y;
            }
            #pragma unroll
            for (int t = 0; t < TNT; t++) {
                float2 bv = *(const float2*)&Ws[k][cb + 16 * t];
                b2[2 * t]     = dup2(bv.x);
                b2[2 * t + 1] = dup2(bv.y);
            }
            #pragma unroll
            for (int i = 0; i < 8; i++)
                #pragma unroll
                for (int j = 0; j < 2 * TNT; j++)
                    acc2[i][j] = ffma2(a2[i], b2[j], acc2[i][j]);
        }
        __syncthreads();
    }

    // epilogue: convert fp32 -> half2 pairs
    #pragma unroll
    for (int i = 0; i < 8; i++) {
        int s = i >> 1, p = i & 1;
        int re = row0 + rb + 16 * s + 2 * p;
        #pragma unroll
        for (int t = 0; t < TNT; t++) {
            float2 e0 = unpack2(acc2[i][2 * t]);
            float2 e1 = unpack2(acc2[i][2 * t + 1]);
            int c = cb + 16 * t;
            if (re < nrows)
                *(__half2*)(T + (size_t)re * NC + c) = __floats2half2_rn(e0.x, e1.x);
            if (re + 1 < nrows)
                *(__half2*)(T + (size_t)(re + 1) * NC + c) = __floats2half2_rn(e0.y, e1.y);
        }
    }
}

// ---------------- aggregate (fp16 gather, fp32 accumulate) ------------------
#define NPB 32

template <bool RELU>
__global__ void k_aggregate128(const __half* __restrict__ T,
                               const int* __restrict__ rowptr,
                               const int2* __restrict__ cw,
                               const float* __restrict__ dinv,
                               const float* __restrict__ bias,
                               float* __restrict__ H, int n) {
    __shared__ int ctr;
    if (threadIdx.x == 0) ctr = 0;
    __syncthreads();
    const int base = blockIdx.x * NPB;
    const int lane = threadIdx.x & 31;

    for (;;) {
        int k;
        if (lane == 0) k = atomicAdd(&ctr, 1);
        k = __shfl_sync(0xFFFFFFFFu, k, 0);
        if (k >= NPB) break;
        int i = base + k;
        if (i >= n) break;

        float dn = dinv[i]; dn *= dn;
        uint2 tv = __ldg((const uint2*)(T + (size_t)i * 128) + lane);
        float2 t0 = __half22float2(*(__half2*)&tv.x);
        float2 t1 = __half22float2(*(__half2*)&tv.y);
        float4 acc = make_float4(t0.x * dn, t0.y * dn, t1.x * dn, t1.y * dn);
        float4 acc1 = make_float4(0.f, 0.f, 0.f, 0.f);

        int j = rowptr[i], end = rowptr[i + 1];
        for (; j + 2 <= end; j += 2) {
            int2 e0 = __ldg(cw + j);
            int2 e1 = __ldg(cw + j + 1);
            float w0 = __int_as_float(e0.y), w1 = __int_as_float(e1.y);
            uint2 r0 = __ldg((const uint2*)(T + (size_t)e0.x * 128) + lane);
            uint2 r1 = __ldg((const uint2*)(T + (size_t)e1.x * 128) + lane);
            float2 a0 = __half22float2(*(__half2*)&r0.x);
            float2 a1 = __half22float2(*(__half2*)&r0.y);
            float2 b0 = __half22float2(*(__half2*)&r1.x);
            float2 b1 = __half22float2(*(__half2*)&r1.y);
            acc.x  = fmaf(w0, a0.x, acc.x);  acc.y  = fmaf(w0, a0.y, acc.y);
            acc.z  = fmaf(w0, a1.x, acc.z);  acc.w  = fmaf(w0, a1.y, acc.w);
            acc1.x = fmaf(w1, b0.x, acc1.x); acc1.y = fmaf(w1, b0.y, acc1.y);
            acc1.z = fmaf(w1, b1.x, acc1.z); acc1.w = fmaf(w1, b1.y, acc1.w);
        }
        if (j < end) {
            int2 e0 = __ldg(cw + j);
            float w0 = __int_as_float(e0.y);
            uint2 r0 = __ldg((const uint2*)(T + (size_t)e0.x * 128) + lane);
            float2 a0 = __half22float2(*(__half2*)&r0.x);
            float2 a1 = __half22float2(*(__half2*)&r0.y);
            acc.x = fmaf(w0, a0.x, acc.x); acc.y = fmaf(w0, a0.y, acc.y);
            acc.z = fmaf(w0, a1.x, acc.z); acc.w = fmaf(w0, a1.y, acc.w);
        }
        acc.x += acc1.x; acc.y += acc1.y; acc.z += acc1.z; acc.w += acc1.w;

        float4 b = __ldg((const float4*)bias + lane);
        acc.x += b.x; acc.y += b.y; acc.z += b.z; acc.w += b.w;
        if (RELU) {
            acc.x = fmaxf(acc.x, 0.f); acc.y = fmaxf(acc.y, 0.f);
            acc.z = fmaxf(acc.z, 0.f); acc.w = fmaxf(acc.w, 0.f);
        }
        ((float4*)(H + (size_t)i * 128))[lane] = acc;
    }
}

__global__ void k_aggregate64(const __half* __restrict__ T,
                              const int* __restrict__ rowptr,
                              const int2* __restrict__ cw,
                              const float* __restrict__ dinv,
                              const float* __restrict__ bias,
                              float* __restrict__ Z, int n) {
    __shared__ int ctr;
    if (threadIdx.x == 0) ctr = 0;
    __syncthreads();
    const int base = blockIdx.x * NPB;
    const int lane = threadIdx.x & 31;

    for (;;) {
        int k;
        if (lane == 0) k = atomicAdd(&ctr, 1);
        k = __shfl_sync(0xFFFFFFFFu, k, 0);
        if (k >= NPB) break;
        int i = base + k;
        if (i >= n) break;

        float dn = dinv[i]; dn *= dn;
        unsigned tv = __ldg((const unsigned*)(T + (size_t)i * 64) + lane);
        float2 t0 = __half22float2(*(__half2*)&tv);
        float2 acc = make_float2(t0.x * dn, t0.y * dn);
        float2 acc1 = make_float2(0.f, 0.f);

        int j = rowptr[i], end = rowptr[i + 1];
        for (; j + 2 <= end; j += 2) {
            int2 e0 = __ldg(cw + j);
            int2 e1 = __ldg(cw + j + 1);
            float w0 = __int_as_float(e0.y), w1 = __int_as_float(e1.y);
            unsigned r0 = __ldg((const unsigned*)(T + (size_t)e0.x * 64) + lane);
            unsigned r1 = __ldg((const unsigned*)(T + (size_t)e1.x * 64) + lane);
            float2 a0 = __half22float2(*(__half2*)&r0);
            float2 b0 = __half22float2(*(__half2*)&r1);
            acc.x  = fmaf(w0, a0.x, acc.x);  acc.y  = fmaf(w0, a0.y, acc.y);
            acc1.x = fmaf(w1, b0.x, acc1.x); acc1.y = fmaf(w1, b0.y, acc1.y);
        }
        if (j < end) {
            int2 e0 = __ldg(cw + j);
            float w0 = __int_as_float(e0.y);
            unsigned r0 = __ldg((const unsigned*)(T + (size_t)e0.x * 64) + lane);
            float2 a0 = __half22float2(*(__half2*)&r0);
            acc.x = fmaf(w0, a0.x, acc.x); acc.y = fmaf(w0, a0.y, acc.y);
        }
        acc.x += acc1.x; acc.y += acc1.y;

        float2 b = __ldg((const float2*)bias + lane);
        acc.x += b.x; acc.y += b.y;
        ((float2*)(Z + (size_t)i * 64))[lane] = acc;
    }
}

// ---------------- decode -----------------------------------------------------
__global__ void k_decode(const float* __restrict__ Z, const int* __restrict__ eli,
                         float* __restrict__ out, int EL) {
    int gt = blockIdx.x * blockDim.x + threadIdx.x;
    int p = gt >> 5;
    int lane = gt & 31;
    if (p >= EL) return;
    int a = eli[p];
    int b = eli[EL + p];
    float2 za = __ldg((const float2*)(Z + (size_t)a * 64) + lane);
    float2 zb = __ldg((const float2*)(Z + (size_t)b * 64) + lane);
    float s = za.x * zb.x + za.y * zb.y;
    #pragma unroll
    for (int o = 16; o; o >>= 1) s += __shfl_xor_sync(0xFFFFFFFFu, s, o);
    if (lane == 0) out[p] = s;
}

// ---------------- launch ----------------------------------------------------
extern "C" void kernel_launch(void* const* d_in, const int* in_sizes, int n_in,
                              void* d_out, int out_size) {
    const float* x   = (const float*)d_in[0];
    const int*   ei  = (const int*)d_in[1];
    const int*   eli = (const int*)d_in[2];
    const float* W1 = (const float*)d_in[3];
    const float* b1 = (const float*)d_in[4];
    const float* W2 = (const float*)d_in[5];
    const float* b2 = (const float*)d_in[6];
    const float* W3 = (const float*)d_in[7];
    const float* b3 = (const float*)d_in[8];
    float* out = (float*)d_out;

    const int N  = in_sizes[0] / DIN;
    const int E  = in_sizes[1] / 2;
    const int EL = in_sizes[2] / 2;
    const int* src = ei;
    const int* dst = ei + E;

    int *cnt, *fill, *rowptr, *bsums;
    int2* cw;
    float *dinv, *H, *Z;
    __half* T;
    cudaGetSymbolAddress((void**)&cnt,    g_cnt);
    cudaGetSymbolAddress((void**)&fill,   g_fill);
    cudaGetSymbolAddress((void**)&rowptr, g_rowptr);
    cudaGetSymbolAddress((void**)&bsums,  g_bsums);
    cudaGetSymbolAddress((void**)&cw,     g_cw);
    cudaGetSymbolAddress((void**)&dinv,   g_dinv);
    cudaGetSymbolAddress((void**)&T,      g_T16);
    cudaGetSymbolAddress((void**)&H,      g_H);
    cudaGetSymbolAddress((void**)&Z,      g_Z);

    const int TB = 256;
    const int nblk = (N + SCAN_B - 1) / SCAN_B;
    const int gblocks = (N + 127) / 128;
    const int ablocks = (N + NPB - 1) / NPB;

    k_zero_count<<<(N + TB - 1) / TB, TB>>>(dst, cnt, fill, N, E);
    k_count<<<(E + TB - 1) / TB, TB>>>(dst, cnt, E);
    k_dinv <<<(N + TB - 1) / TB, TB>>>(cnt, dinv, N);
    k_gemm3<128><<<gblocks, 128>>>(x, W1, T, N);          // layer-1 GEMM
    k_scan1<<<nblk, SCAN_B>>>(cnt, rowptr, bsums, N);
    k_scan2<<<1, 1>>>(bsums, nblk, rowptr, N);
    k_scan3<<<(N + TB - 1) / TB, TB>>>(rowptr, bsums, N);
    k_fill <<<(E + TB - 1) / TB, TB>>>(src, dst, rowptr, fill, dinv, cw, E);

    // layer 1 aggregate
    k_aggregate128<true><<<ablocks, TB>>>(T, rowptr, cw, dinv, b1, H, N);
    // layer 2
    k_gemm3<128><<<gblocks, 128>>>(H, W2, T, N);
    k_aggregate128<true><<<ablocks, TB>>>(T, rowptr, cw, dinv, b2, H, N);
    // layer 3
    k_gemm3<64><<<gblocks, 128>>>(H, W3, T, N);
    k_aggregate64<<<ablocks, TB>>>(T, rowptr, cw, dinv, b3, Z, N);

    // decode
    k_decode<<<(int)(((size_t)EL * 32 + TB - 1) / TB), TB>>>(Z, eli, out, EL);
}